// round 1
// baseline (speedup 1.0000x reference)
#include <cuda_runtime.h>
#include <math.h>

#define GS        32          // gaussian split chunks
#define MAXN      16384       // max gaussians
#define MAXOUT    49152       // max output elements (3*128*128)
#define ROWS_PER_BLK 4

// Per-gaussian precomputed params (SoA, float4-friendly)
__device__ float4 d_gA[MAXN];                 // {m00, m01, m10, m11}  (prescaled)
__device__ float4 d_gB[MAXN];                 // {-bu, -bv, cr, cg}
__device__ float  d_gC[MAXN];                 // cb
__device__ float  d_partial[GS * MAXOUT];     // per-chunk partial images

__device__ __forceinline__ float ex2_neg(float t) {
    float r, nt = -t;
    asm("ex2.approx.ftz.f32 %0, %1;" : "=f"(r) : "f"(nt));
    return r;
}

// ---------------------------------------------------------------------------
// Prep: fold rotation/scale/center/alpha into 9 floats per gaussian.
// u' = px*m00 + py*m01 + bun ; v' = px*m10 + py*m11 + bvn
// with rows prescaled by SF = sqrt(0.5*log2(e)) so w = 2^-(u'^2+v'^2).
// ---------------------------------------------------------------------------
__global__ void prep_kernel(const float* __restrict__ pos,
                            const float* __restrict__ col,
                            const float* __restrict__ lsc,
                            const float* __restrict__ rot,
                            const float* __restrict__ alph,
                            const int*   __restrict__ pnum,
                            int N)
{
    int g = blockIdx.x * blockDim.x + threadIdx.x;
    if (g >= N) return;
    int na = pnum ? *pnum : N;

    float gx = pos[2*g], gy = pos[2*g+1];
    float sx = expf(lsc[2*g])   + 1e-6f;
    float sy = expf(lsc[2*g+1]) + 1e-6f;
    float r  = rot[g];
    float c  = cosf(r), s = sinf(r);

    const float SF = 0.8493218002880191f;   // sqrt(0.5 * log2(e))
    float isx = SF / sx, isy = SF / sy;
    float m00 = c * isx,  m01 = s * isx;
    float m10 = -s * isy, m11 = c * isy;
    float bun = -(gx*m00 + gy*m01);
    float bvn = -(gx*m10 + gy*m11);

    float a  = (g < na) ? alph[g] : 0.0f;
    float cr = a * col[3*g], cg = a * col[3*g+1], cb = a * col[3*g+2];

    d_gA[g] = make_float4(m00, m01, m10, m11);
    d_gB[g] = make_float4(bun, bvn, cr, cg);
    d_gC[g] = cb;
}

// ---------------------------------------------------------------------------
// Main splat: block = one column-strip of 4 rows x W cols, one gaussian chunk.
// thread t = column t; per gaussian the column part (cu, cv) is computed once
// and reused by all 4 rows.
// ---------------------------------------------------------------------------
__global__ void __launch_bounds__(128)
splat_kernel(int N, int H, int W, int chunkSize, int HW)
{
    __shared__ float4 sA[128];
    __shared__ float4 sB[128];
    __shared__ float  sC[128];

    const int col     = threadIdx.x;          // blockDim.x == W (==128)
    const int rowBase = blockIdx.x * ROWS_PER_BLK;
    const int chunk   = blockIdx.y;

    const float px = -1.0f + 2.0f * col / (float)(W - 1);
    float py[ROWS_PER_BLK];
#pragma unroll
    for (int r = 0; r < ROWS_PER_BLK; r++) {
        int row = rowBase + r;
        if (row > H - 1) row = H - 1;
        py[r] = -1.0f + 2.0f * row / (float)(H - 1);
    }

    float aR[ROWS_PER_BLK] = {0,0,0,0};
    float aG[ROWS_PER_BLK] = {0,0,0,0};
    float aB[ROWS_PER_BLK] = {0,0,0,0};

    const int g0 = chunk * chunkSize;
    int g1 = g0 + chunkSize; if (g1 > N) g1 = N;

    for (int gbase = g0; gbase < g1; gbase += 128) {
        int idx = gbase + threadIdx.x;
        if (idx < g1) {
            sA[threadIdx.x] = d_gA[idx];
            sB[threadIdx.x] = d_gB[idx];
            sC[threadIdx.x] = d_gC[idx];
        } else {
            sA[threadIdx.x] = make_float4(1.f, 0.f, 0.f, 1.f);
            sB[threadIdx.x] = make_float4(0.f, 0.f, 0.f, 0.f);
            sC[threadIdx.x] = 0.f;
        }
        __syncthreads();

        int cnt = g1 - gbase; if (cnt > 128) cnt = 128;
#pragma unroll 2
        for (int j = 0; j < cnt; j++) {
            float4 A  = sA[j];
            float4 B  = sB[j];
            float  cb = sC[j];
            float cu = fmaf(px, A.x, B.x);   // px*m00 - bu
            float cv = fmaf(px, A.z, B.y);   // px*m10 - bv
#pragma unroll
            for (int r = 0; r < ROWS_PER_BLK; r++) {
                float u = fmaf(py[r], A.y, cu);
                float v = fmaf(py[r], A.w, cv);
                float t = fmaf(v, v, u * u);
                float e = ex2_neg(t);        // 2^-t == exp(-0.5*q)
                aR[r] = fmaf(e, B.z, aR[r]);
                aG[r] = fmaf(e, B.w, aG[r]);
                aB[r] = fmaf(e, cb,  aB[r]);
            }
        }
        __syncthreads();
    }

    // write deterministic per-chunk partials
    float* base = d_partial + (size_t)chunk * 3 * HW;
#pragma unroll
    for (int r = 0; r < ROWS_PER_BLK; r++) {
        int row = rowBase + r;
        if (row < H) {
            int pix = row * W + col;
            base[0 * HW + pix] = aR[r];
            base[1 * HW + pix] = aG[r];
            base[2 * HW + pix] = aB[r];
        }
    }
}

// ---------------------------------------------------------------------------
// Reduce GS partials, subtract 1.
// ---------------------------------------------------------------------------
__global__ void reduce_kernel(float* __restrict__ out, int total)
{
    int i = blockIdx.x * blockDim.x + threadIdx.x;
    if (i >= total) return;
    float s = -1.0f;
#pragma unroll
    for (int k = 0; k < GS; k++)
        s += d_partial[(size_t)k * MAXOUT + 0];  // placeholder, replaced below
    out[i] = s;
}

// NOTE: reduce must index by actual out_size stride, so use this version:
__global__ void reduce_kernel2(float* __restrict__ out, int total)
{
    int i = blockIdx.x * blockDim.x + threadIdx.x;
    if (i >= total) return;
    float s = -1.0f;
#pragma unroll
    for (int k = 0; k < GS; k++)
        s += d_partial[(size_t)k * total + i];
    out[i] = s;
}

extern "C" void kernel_launch(void* const* d_in, const int* in_sizes, int n_in,
                              void* d_out, int out_size)
{
    const float* pos  = (const float*)d_in[0];   // [1,N,2]
    const float* col  = (const float*)d_in[1];   // [1,N,3]
    const float* lsc  = (const float*)d_in[2];   // [1,N,2]
    const float* rot  = (const float*)d_in[3];   // [1,N]
    const float* alph = (const float*)d_in[4];   // [1,N]
    const int*   pnum = (n_in > 7) ? (const int*)d_in[7] : nullptr;

    int N  = in_sizes[0] / 2;
    int HW = out_size / 3;
    int W  = (int)(sqrt((double)HW) + 0.5);
    int H  = HW / W;
    float* out = (float*)d_out;

    prep_kernel<<<(N + 127) / 128, 128>>>(pos, col, lsc, rot, alph, pnum, N);

    int chunkSize = (N + GS - 1) / GS;
    dim3 grid((H + ROWS_PER_BLK - 1) / ROWS_PER_BLK, GS);
    splat_kernel<<<grid, W>>>(N, H, W, chunkSize, HW);

    reduce_kernel2<<<(out_size + 255) / 256, 256>>>(out, out_size);
}